// round 4
// baseline (speedup 1.0000x reference)
#include <cuda_runtime.h>

#define Hh 64
#define Ww 64
#define CIN 16
#define COUT 32
// smem float offsets
#define WS_OFF   0          // 4 locs * 32 o * 146  = 18688 floats
#define WS_OSTR  146        // per-o row stride (floats); /2 = 73 u64 (odd -> bank-spread)
#define WS_LSTR  (32*WS_OSTR)
#define XS_OFF   18688      // 32 b * 289
#define XS_BSTR  289        // 48 ck * 6 cols + 1 pad
#define BS_OFF   27936      // 128 bias floats
#define SMEM_FLOATS 28064   // 112256 bytes

typedef unsigned long long u64;

__device__ __forceinline__ void fma2(u64& d, u64 a, u64 b) {
    asm("fma.rn.f32x2 %0, %1, %2, %0;" : "+l"(d) : "l"(a), "l"(b));
}
__device__ __forceinline__ u64 packf2(float a, float b) {
    u64 r; asm("mov.b64 %0, {%1, %2};" : "=l"(r) : "f"(a), "f"(b)); return r;
}
__device__ __forceinline__ void unpackf2(u64 d, float& lo, float& hi) {
    asm("mov.b64 {%0, %1}, %2;" : "=f"(lo), "=f"(hi) : "l"(d));
}

__global__ __launch_bounds__(128) void xonv_kernel(
    const float* __restrict__ x,        // (32, 16, 64, 64)
    const float* __restrict__ weights,  // (64, 64, 32, 16, 3, 3)
    const float* __restrict__ bias,     // (64, 64, 32)
    float* __restrict__ out)            // (32, 32, 64, 64)
{
    extern __shared__ float sm[];
    float* ws = sm + WS_OFF;
    float* xs = sm + XS_OFF;
    float* bs = sm + BS_OFF;

    const int tid  = threadIdx.x;
    const int lane = tid & 31;
    const int wid  = tid >> 5;           // warp = location offset 0..3
    const int h    = blockIdx.x >> 4;
    const int w0   = (blockIdx.x & 15) * 4;
    const int loc0 = h * Ww + w0;

    // ---------------- stage weights: 4 locs, coalesced LDG.128 -> row-major ws ----------
    {
        const float4* wg = (const float4*)weights + (size_t)loc0 * 1152;
        #pragma unroll 4
        for (int i = 0; i < 36; ++i) {
            int g   = tid + 128 * i;          // 0..4607 float4
            float4 v = wg[g];
            int l   = g / 1152;
            int rem = g - l * 1152;
            int o   = rem / 36;
            int pc  = rem - o * 36;
            float* dst = ws + (l * 32 + o) * WS_OSTR + pc * 4;
            *(float2*)(dst)     = make_float2(v.x, v.y);
            *(float2*)(dst + 2) = make_float2(v.z, v.w);
        }
    }
    // bias: 128 contiguous floats
    bs[tid] = bias[(size_t)loc0 * COUT + tid];

    // ---------------- stage x slab: rows (b,ck), 6 cols (w0-1..w0+4), ~coalesced -------
    {
        const int dr = lane / 6;              // 0..4 (lane<30)
        const int c  = lane - dr * 6;         // 0..5
        for (int it = 0; it < 77; ++it) {
            int row = it * 20 + wid * 5 + dr;
            if (lane < 30 && row < 1536) {
                int b  = row / 48;
                int ck = row - b * 48;
                int ci = ck / 3;
                int kh = ck - ci * 3;
                int hh = h + kh - 1;
                int ww = w0 + c - 1;
                float v = 0.f;
                if ((unsigned)hh < 64u && (unsigned)ww < 64u)
                    v = x[(((size_t)b * CIN + ci) * Hh + hh) * Ww + ww];
                xs[b * XS_BSTR + ck * 6 + c] = v;
            }
        }
    }
    __syncthreads();

    // ---------------- compute: warp=loc, lane=(bg 8)x(og 4), tile 4b x 8o --------------
    const int bg = lane >> 2;                 // 0..7
    const int og = lane & 3;                  // 0..3
    const u64* wl64 = (const u64*)(ws + wid * WS_LSTR);  // this loc's weights as u64
    const float* xb = xs + wid;               // col base = wid (cols wid..wid+2)

    u64 acc[4][8];                            // [jb][jo], lanes = even/odd p
    #pragma unroll
    for (int a = 0; a < 4; ++a)
        #pragma unroll
        for (int b = 0; b < 8; ++b) acc[a][b] = 0ull;

    #pragma unroll 1
    for (int ckb = 0; ckb < 24; ++ckb) {      // 2 ck (=6 p) per block
        // x: 6 floats per b, pack into 3 p-pairs
        u64 xp[4][3];
        #pragma unroll
        for (int jb = 0; jb < 4; ++jb) {
            const float* xr = xb + (bg * 4 + jb) * XS_BSTR + ckb * 12;
            float a0 = xr[0], a1 = xr[1], a2 = xr[2];
            float b0 = xr[6], b1 = xr[7], b2 = xr[8];
            xp[jb][0] = packf2(a0, a1);
            xp[jb][1] = packf2(a2, b0);
            xp[jb][2] = packf2(b1, b2);
        }
        // w: per jo, 3 consecutive u64 p-pairs; o = jo*4 + og
        #pragma unroll
        for (int jo = 0; jo < 8; ++jo) {
            int o = jo * 4 + og;
            const u64* wr = wl64 + o * 73 + 3 * ckb;
            u64 w0v = wr[0], w1v = wr[1], w2v = wr[2];
            #pragma unroll
            for (int jb = 0; jb < 4; ++jb) {
                fma2(acc[jb][jo], xp[jb][0], w0v);
                fma2(acc[jb][jo], xp[jb][1], w1v);
                fma2(acc[jb][jo], xp[jb][2], w2v);
            }
        }
    }
    __syncthreads();   // all warps done reading ws/xs; reuse ws as gather buffer

    // ---------------- gather 4 locs via smem, then STG.128 over the w-strip ------------
    {
        const int xr_s = bg & 3;              // store-side xor swizzle
        #pragma unroll
        for (int jo = 0; jo < 8; ++jo) {
            int o = jo * 4 + og;
            float bv = bs[wid * 32 + o];
            #pragma unroll
            for (int jb = 0; jb < 4; ++jb) {
                float lo, hi;
                unpackf2(acc[jb][jo], lo, hi);
                int bo = (bg * 4 + jb) * 32 + o;
                ws[bo * 4 + (wid ^ xr_s)] = lo + hi + bv;
            }
        }
    }
    __syncthreads();

    {
        #pragma unroll
        for (int k = 0; k < 8; ++k) {
            int bo  = tid + 128 * k;          // (b*32+o), 0..1023
            int xr  = (bo >> 7) & 3;          // = bg&3 of the storing thread
            float4 v;
            v.x = ws[bo * 4 + (0 ^ xr)];
            v.y = ws[bo * 4 + (1 ^ xr)];
            v.z = ws[bo * 4 + (2 ^ xr)];
            v.w = ws[bo * 4 + (3 ^ xr)];
            *(float4*)(out + (size_t)bo * 4096 + loc0) = v;
        }
    }
}

extern "C" void kernel_launch(void* const* d_in, const int* in_sizes, int n_in,
                              void* d_out, int out_size) {
    const float* x       = (const float*)d_in[0];
    const float* weights = (const float*)d_in[1];
    const float* bias    = (const float*)d_in[2];
    float* out = (float*)d_out;
    (void)in_sizes; (void)n_in; (void)out_size;

    // >48KB dynamic smem: set once per call (harness calls uncaptured first, so the
    // attribute is already in effect when graph capture replays the launch).
    cudaFuncSetAttribute(xonv_kernel, cudaFuncAttributeMaxDynamicSharedMemorySize,
                         SMEM_FLOATS * 4);
    xonv_kernel<<<1024, 128, SMEM_FLOATS * 4>>>(x, weights, bias, out);
}

// round 5
// speedup vs baseline: 1.5577x; 1.5577x over previous
#include <cuda_runtime.h>

typedef unsigned long long u64;

#define NLOC 4
#define THREADS 256
// smem byte offsets
#define WS_ROWSTRIDE 194            // u64 per (loc,ckB) row-group: 32*6 + 2 pad
#define WS_U64 (NLOC * 12 * WS_ROWSTRIDE)   // 9312 u64
#define WS_BYTES (WS_U64 * 8)               // 74496
#define XS_BSTR 289                 // floats per b row: 48 ck * 6 cols + 1
#define XS_FLOATS (32 * XS_BSTR)    // 9248
#define XS_BYTES (XS_FLOATS * 4)    // 36992
#define BS_BYTES 512                // 128 floats
#define SMEM_BYTES (WS_BYTES + XS_BYTES + BS_BYTES)   // 112000

__device__ __forceinline__ void fma2(u64& d, u64 a, u64 b) {
    asm("fma.rn.f32x2 %0, %1, %2, %0;" : "+l"(d) : "l"(a), "l"(b));
}
__device__ __forceinline__ u64 packf2(float a, float b) {
    u64 r; asm("mov.b64 %0, {%1, %2};" : "=l"(r) : "f"(a), "f"(b)); return r;
}
__device__ __forceinline__ void unpackf2(u64 d, float& lo, float& hi) {
    asm("mov.b64 {%0, %1}, %2;" : "=f"(lo), "=f"(hi) : "l"(d));
}

__global__ __launch_bounds__(THREADS, 2) void xonv_kernel(
    const float* __restrict__ x,        // (32, 16, 64, 64)
    const float* __restrict__ weights,  // (64, 64, 32, 16, 3, 3)
    const float* __restrict__ bias,     // (64, 64, 32)
    float* __restrict__ out)            // (32, 32, 64, 64)
{
    extern __shared__ __align__(16) char smraw[];
    u64*   ws64 = (u64*)smraw;
    float* xs   = (float*)(smraw + WS_BYTES);
    float* bs   = (float*)(smraw + WS_BYTES + XS_BYTES);

    const int tid  = threadIdx.x;
    const int lane = tid & 31;
    const int wid  = tid >> 5;                 // 0..7
    const int h    = blockIdx.x >> 4;
    const int w0   = (blockIdx.x & 15) * NLOC; // 0,4,...,60
    const int loc0 = h * 64 + w0;

    // ============ stage weights: coalesced LDG.128 -> aligned u64-pair layout ============
    // dst u64 index: (l*12 + ckB)*194 + o*6 + 2*(pc%3)   [ckB = pc/3]
    {
        const float4* wg = (const float4*)weights + (size_t)loc0 * 1152;
        #pragma unroll
        for (int i = 0; i < 18; ++i) {
            int g   = tid + THREADS * i;        // 0..4607
            float4 v = wg[g];
            int l   = g / 1152;
            int rem = g - l * 1152;
            int o   = rem / 36;
            int pc  = rem - o * 36;
            int ckB = pc / 3;
            int m   = pc - ckB * 3;
            int idx = (l * 12 + ckB) * WS_ROWSTRIDE + o * 6 + 2 * m;  // even -> 16B aligned
            *(float4*)(ws64 + idx) = v;
        }
    }
    if (tid < 128) bs[tid] = bias[(size_t)loc0 * 32 + tid];

    // ============ stage x slab: rows (b,ck), 6 cols (w0-1..w0+4) ============
    {
        const int dr = lane / 6;               // 0..4 for lane<30
        const int c  = lane - dr * 6;          // 0..5
        #pragma unroll 4
        for (int it = 0; it < 39; ++it) {
            int row = it * 40 + wid * 5 + dr;
            if (lane < 30 && row < 1536) {
                int b  = row / 48;
                int ck = row - b * 48;
                int ci = ck / 3;
                int kh = ck - ci * 3;
                int hh = h + kh - 1;
                int ww = w0 + c - 1;
                float v = 0.f;
                if ((unsigned)hh < 64u && (unsigned)ww < 64u)
                    v = x[(((size_t)b * 16 + ci) * 64 + hh) * 64 + ww];
                xs[b * XS_BSTR + ck * 6 + c] = v;
            }
        }
    }
    __syncthreads();

    // ============ compute: warp = (loc l, b-half), thread = 2b x 8o ============
    const int l  = wid >> 1;
    const int bh = wid & 1;
    const int bg = lane >> 2;                  // 0..7
    const int og = lane & 3;                   // 0..3
    const int b0 = bh * 16 + bg * 2;

    const float* xb    = xs + b0 * XS_BSTR + l;
    const u64*   wbase = ws64 + (size_t)l * 12 * WS_ROWSTRIDE + og * 6;

    u64 acc[2][8];
    #pragma unroll
    for (int a = 0; a < 2; ++a)
        #pragma unroll
        for (int j = 0; j < 8; ++j) acc[a][j] = 0ull;

    #pragma unroll 2
    for (int ckB = 0; ckB < 12; ++ckB) {
        // x: 4 ck (12 p) per jb -> 6 packed p-pairs
        u64 xp[2][6];
        #pragma unroll
        for (int jb = 0; jb < 2; ++jb) {
            const float* xr = xb + jb * XS_BSTR + ckB * 24;
            float f0 = xr[0],  f1 = xr[1],  f2 = xr[2];
            float f6 = xr[6],  f7 = xr[7],  f8 = xr[8];
            float fc = xr[12], fd = xr[13], fe = xr[14];
            float fi = xr[18], fj = xr[19], fk = xr[20];
            xp[jb][0] = packf2(f0, f1);
            xp[jb][1] = packf2(f2, f6);
            xp[jb][2] = packf2(f7, f8);
            xp[jb][3] = packf2(fc, fd);
            xp[jb][4] = packf2(fe, fi);
            xp[jb][5] = packf2(fj, fk);
        }
        const u64* wck = wbase + ckB * WS_ROWSTRIDE;
        #pragma unroll
        for (int jo = 0; jo < 8; ++jo) {
            const u64* wr = wck + jo * 24;     // o = jo*4+og -> o*6 = jo*24 + og*6
            ulonglong2 wa = *(const ulonglong2*)(wr);
            ulonglong2 wb = *(const ulonglong2*)(wr + 2);
            ulonglong2 wc = *(const ulonglong2*)(wr + 4);
            #pragma unroll
            for (int jb = 0; jb < 2; ++jb) {
                fma2(acc[jb][jo], xp[jb][0], wa.x);
                fma2(acc[jb][jo], xp[jb][1], wa.y);
                fma2(acc[jb][jo], xp[jb][2], wb.x);
                fma2(acc[jb][jo], xp[jb][3], wb.y);
                fma2(acc[jb][jo], xp[jb][4], wc.x);
                fma2(acc[jb][jo], xp[jb][5], wc.y);
            }
        }
    }
    __syncthreads();   // done reading ws/xs; reuse ws as gather buffer

    // ============ gather via smem (xor-swizzled), then STG.128 over w-strip ============
    float* gat = (float*)ws64;                 // 1024 bo * 4 floats = 16KB
    {
        const int s = bg & 3;
        #pragma unroll
        for (int jo = 0; jo < 8; ++jo) {
            int o = jo * 4 + og;
            float bv = bs[l * 32 + o];
            #pragma unroll
            for (int jb = 0; jb < 2; ++jb) {
                int b  = b0 + jb;
                int bo = b * 32 + o;
                float lo, hi;
                unpackf2(acc[jb][jo], lo, hi);
                gat[bo * 4 + (l ^ s)] = lo + hi + bv;
            }
        }
    }
    __syncthreads();

    {
        #pragma unroll
        for (int k = 0; k < 4; ++k) {
            int bo = tid + THREADS * k;        // 0..1023
            int xr = (bo >> 6) & 3;            // warp-uniform writer swizzle
            float4 v = *(const float4*)(gat + bo * 4);
            float p0, p1, p2, p3;
            if (xr == 0)      { p0 = v.x; p1 = v.y; p2 = v.z; p3 = v.w; }
            else if (xr == 1) { p0 = v.y; p1 = v.x; p2 = v.w; p3 = v.z; }
            else if (xr == 2) { p0 = v.z; p1 = v.w; p2 = v.x; p3 = v.y; }
            else              { p0 = v.w; p1 = v.z; p2 = v.y; p3 = v.x; }
            float4 ov = make_float4(p0, p1, p2, p3);
            *(float4*)(out + (size_t)bo * 4096 + loc0) = ov;
        }
    }
}

extern "C" void kernel_launch(void* const* d_in, const int* in_sizes, int n_in,
                              void* d_out, int out_size) {
    const float* x       = (const float*)d_in[0];
    const float* weights = (const float*)d_in[1];
    const float* bias    = (const float*)d_in[2];
    float* out = (float*)d_out;
    (void)in_sizes; (void)n_in; (void)out_size;

    cudaFuncSetAttribute(xonv_kernel, cudaFuncAttributeMaxDynamicSharedMemorySize,
                         SMEM_BYTES);
    xonv_kernel<<<1024, THREADS, SMEM_BYTES>>>(x, weights, bias, out);
}